// round 8
// baseline (speedup 1.0000x reference)
#include <cuda_runtime.h>
#include <cuda_bf16.h>

#define BATCH   8
#define NSEQ    1024
#define DMODEL  512
#define NHEAD   8
#define DHEAD   64

// Scratch for Q/K/V projections (device globals: allocation-free)
__device__ float g_q[BATCH * NSEQ * DMODEL];
__device__ float g_k[BATCH * NSEQ * DMODEL];
__device__ float g_v[BATCH * NSEQ * DMODEL];

// ---------------------------------------------------------------------------
// Kernel 1: fused QKV projection.  Y = x @ W + b   (W stored [in, out])
// M = B*N = 8192, K = 512, Nout = 512.  blockIdx.z selects q/k/v.
// 64x64 output tile per block, 256 threads, 4x4 register tile per thread.
// ---------------------------------------------------------------------------
__global__ __launch_bounds__(256) void qkv_kernel(
    const float* __restrict__ x,
    const float* __restrict__ Wq, const float* __restrict__ bq,
    const float* __restrict__ Wk, const float* __restrict__ bk,
    const float* __restrict__ Wv, const float* __restrict__ bv)
{
    __shared__ float As[16 * 64];   // As[k][m]  (x tile, transposed)
    __shared__ float Bs[16 * 64];   // Bs[k][n]  (W tile, natural)

    const float* W; const float* bias; float* out;
    const int z = blockIdx.z;
    if (z == 0)      { W = Wq; bias = bq; out = g_q; }
    else if (z == 1) { W = Wk; bias = bk; out = g_k; }
    else             { W = Wv; bias = bv; out = g_v; }

    const int n0 = blockIdx.x * 64;
    const int m0 = blockIdx.y * 64;
    const int tid = threadIdx.x;
    const int tx = tid & 15, ty = tid >> 4;

    // A-load mapping: one float4 per thread per K-step
    const int am = tid >> 2;          // row within 64
    const int ak = (tid & 3) * 4;     // k segment start
    // B-load mapping: one float4 per thread per K-step
    const int bkr = tid >> 4;         // k row within 16
    const int bn  = (tid & 15) * 4;   // n segment start

    float acc[16];
    #pragma unroll
    for (int i = 0; i < 16; ++i) acc[i] = 0.f;

    for (int k0 = 0; k0 < DMODEL; k0 += 16) {
        const float4 a4 = *(const float4*)&x[(m0 + am) * DMODEL + k0 + ak];
        const float4 b4 = *(const float4*)&W[(k0 + bkr) * DMODEL + n0 + bn];
        __syncthreads();   // previous compute done reading smem
        As[(ak + 0) * 64 + am] = a4.x;
        As[(ak + 1) * 64 + am] = a4.y;
        As[(ak + 2) * 64 + am] = a4.z;
        As[(ak + 3) * 64 + am] = a4.w;
        *(float4*)&Bs[bkr * 64 + bn] = b4;
        __syncthreads();

        #pragma unroll
        for (int kk = 0; kk < 16; ++kk) {
            const float4 av = *(const float4*)&As[kk * 64 + 4 * ty];
            const float4 bv4 = *(const float4*)&Bs[kk * 64 + 4 * tx];
            acc[ 0] += av.x * bv4.x; acc[ 1] += av.x * bv4.y;
            acc[ 2] += av.x * bv4.z; acc[ 3] += av.x * bv4.w;
            acc[ 4] += av.y * bv4.x; acc[ 5] += av.y * bv4.y;
            acc[ 6] += av.y * bv4.z; acc[ 7] += av.y * bv4.w;
            acc[ 8] += av.z * bv4.x; acc[ 9] += av.z * bv4.y;
            acc[10] += av.z * bv4.z; acc[11] += av.z * bv4.w;
            acc[12] += av.w * bv4.x; acc[13] += av.w * bv4.y;
            acc[14] += av.w * bv4.z; acc[15] += av.w * bv4.w;
        }
    }

    const float4 bb = *(const float4*)&bias[n0 + 4 * tx];
    #pragma unroll
    for (int i = 0; i < 4; ++i) {
        float4 r;
        r.x = acc[4 * i + 0] + bb.x;
        r.y = acc[4 * i + 1] + bb.y;
        r.z = acc[4 * i + 2] + bb.z;
        r.w = acc[4 * i + 3] + bb.w;
        *(float4*)&out[(m0 + 4 * ty + i) * DMODEL + n0 + 4 * tx] = r;
    }
}

// ---------------------------------------------------------------------------
// Kernel 2: flash attention (no 1/sqrt(dh) scaling, per reference).
// One block per (b, h, 64-query tile). 256 threads, 4x4 register tiles.
// Smem: Qt (Q transposed, persistent), KP (K transposed, then aliased as P),
//       Vs (V natural). Exactly 48 KB static.
// ---------------------------------------------------------------------------
__global__ __launch_bounds__(256, 2) void attn_kernel(float* __restrict__ out)
{
    __shared__ float Qt[64 * 64];   // Qt[d][q]
    __shared__ float KP[64 * 64];   // Kt[d][k]  -> later P[q][k]
    __shared__ float Vs[64 * 64];   // Vs[k][d]

    const int bh = blockIdx.x;            // 0..63
    const int b = bh >> 3, h = bh & 7;
    const int q0 = blockIdx.y * 64;
    const int tid = threadIdx.x;
    const int tx = tid & 15, ty = tid >> 4;

    const float* qb = g_q + (b * NSEQ) * DMODEL + h * DHEAD;
    const float* kb = g_k + (b * NSEQ) * DMODEL + h * DHEAD;
    const float* vb = g_v + (b * NSEQ) * DMODEL + h * DHEAD;

    const int lr = tid >> 2;          // tile row this thread loads (0..63)
    const int ds = (tid & 3) * 16;    // d-segment start

    // Load Q tile transposed (once)
    {
        const float* src = qb + (q0 + lr) * DMODEL + ds;
        #pragma unroll
        for (int u = 0; u < 4; ++u) {
            const float4 v4 = *(const float4*)(src + 4 * u);
            const int d = ds + 4 * u;
            Qt[(d + 0) * 64 + lr] = v4.x;
            Qt[(d + 1) * 64 + lr] = v4.y;
            Qt[(d + 2) * 64 + lr] = v4.z;
            Qt[(d + 3) * 64 + lr] = v4.w;
        }
    }

    float o[16];
    #pragma unroll
    for (int i = 0; i < 16; ++i) o[i] = 0.f;
    float mrow[4] = {-1e30f, -1e30f, -1e30f, -1e30f};
    float lrow[4] = {0.f, 0.f, 0.f, 0.f};

    for (int kt = 0; kt < NSEQ / 64; ++kt) {
        const int k0 = kt * 64;
        __syncthreads();   // previous PV done reading KP/Vs (also covers Qt init)

        // Load K transposed + V natural
        {
            const float* ksrc = kb + (k0 + lr) * DMODEL + ds;
            const float* vsrc = vb + (k0 + lr) * DMODEL + ds;
            #pragma unroll
            for (int u = 0; u < 4; ++u) {
                const float4 v4 = *(const float4*)(ksrc + 4 * u);
                const int d = ds + 4 * u;
                KP[(d + 0) * 64 + lr] = v4.x;
                KP[(d + 1) * 64 + lr] = v4.y;
                KP[(d + 2) * 64 + lr] = v4.z;
                KP[(d + 3) * 64 + lr] = v4.w;
                *(float4*)&Vs[lr * 64 + ds + 4 * u] = *(const float4*)(vsrc + 4 * u);
            }
        }
        __syncthreads();

        // S = Q @ K^T  (no scaling)
        float s[16];
        #pragma unroll
        for (int i = 0; i < 16; ++i) s[i] = 0.f;
        #pragma unroll 8
        for (int d = 0; d < 64; ++d) {
            const float4 a = *(const float4*)&Qt[d * 64 + 4 * ty];
            const float4 c = *(const float4*)&KP[d * 64 + 4 * tx];
            s[ 0] += a.x * c.x; s[ 1] += a.x * c.y; s[ 2] += a.x * c.z; s[ 3] += a.x * c.w;
            s[ 4] += a.y * c.x; s[ 5] += a.y * c.y; s[ 6] += a.y * c.z; s[ 7] += a.y * c.w;
            s[ 8] += a.z * c.x; s[ 9] += a.z * c.y; s[10] += a.z * c.z; s[11] += a.z * c.w;
            s[12] += a.w * c.x; s[13] += a.w * c.y; s[14] += a.w * c.z; s[15] += a.w * c.w;
        }

        // Online softmax (row reductions across the 16 tx lanes of each half-warp)
        #pragma unroll
        for (int i = 0; i < 4; ++i) {
            float mt = fmaxf(fmaxf(s[4 * i + 0], s[4 * i + 1]),
                             fmaxf(s[4 * i + 2], s[4 * i + 3]));
            #pragma unroll
            for (int off = 1; off < 16; off <<= 1)
                mt = fmaxf(mt, __shfl_xor_sync(0xffffffffu, mt, off));
            const float mnew = fmaxf(mrow[i], mt);
            const float corr = __expf(mrow[i] - mnew);
            mrow[i] = mnew;
            float rs = 0.f;
            #pragma unroll
            for (int j = 0; j < 4; ++j) {
                const float p = __expf(s[4 * i + j] - mnew);
                s[4 * i + j] = p;
                rs += p;
            }
            #pragma unroll
            for (int off = 1; off < 16; off <<= 1)
                rs += __shfl_xor_sync(0xffffffffu, rs, off);
            lrow[i] = lrow[i] * corr + rs;
            #pragma unroll
            for (int j = 0; j < 4; ++j) o[4 * i + j] *= corr;
        }

        __syncthreads();   // all S reads of KP (as K) done
        // Write P into the dead K buffer, natural layout P[q][k]
        #pragma unroll
        for (int i = 0; i < 4; ++i)
            *(float4*)&KP[(4 * ty + i) * 64 + 4 * tx] =
                make_float4(s[4 * i + 0], s[4 * i + 1], s[4 * i + 2], s[4 * i + 3]);
        __syncthreads();

        // O += P @ V
        #pragma unroll 8
        for (int kk = 0; kk < 64; ++kk) {
            const float4 v4 = *(const float4*)&Vs[kk * 64 + 4 * tx];
            const float p0 = KP[(4 * ty + 0) * 64 + kk];
            const float p1 = KP[(4 * ty + 1) * 64 + kk];
            const float p2 = KP[(4 * ty + 2) * 64 + kk];
            const float p3 = KP[(4 * ty + 3) * 64 + kk];
            o[ 0] += p0 * v4.x; o[ 1] += p0 * v4.y; o[ 2] += p0 * v4.z; o[ 3] += p0 * v4.w;
            o[ 4] += p1 * v4.x; o[ 5] += p1 * v4.y; o[ 6] += p1 * v4.z; o[ 7] += p1 * v4.w;
            o[ 8] += p2 * v4.x; o[ 9] += p2 * v4.y; o[10] += p2 * v4.z; o[11] += p2 * v4.w;
            o[12] += p3 * v4.x; o[13] += p3 * v4.y; o[14] += p3 * v4.z; o[15] += p3 * v4.w;
        }
    }

    // Normalize and store
    float* ob = out + ((b * NSEQ) + q0) * DMODEL + h * DHEAD;
    #pragma unroll
    for (int i = 0; i < 4; ++i) {
        const float inv = 1.0f / lrow[i];
        const float4 r = make_float4(o[4 * i + 0] * inv, o[4 * i + 1] * inv,
                                     o[4 * i + 2] * inv, o[4 * i + 3] * inv);
        *(float4*)&ob[(4 * ty + i) * DMODEL + 4 * tx] = r;
    }
}

// ---------------------------------------------------------------------------
extern "C" void kernel_launch(void* const* d_in, const int* in_sizes, int n_in,
                              void* d_out, int out_size)
{
    (void)in_sizes; (void)n_in; (void)out_size;
    const float* x  = (const float*)d_in[0];
    const float* Wq = (const float*)d_in[1];
    const float* bq = (const float*)d_in[2];
    const float* Wk = (const float*)d_in[3];
    const float* bk = (const float*)d_in[4];
    const float* Wv = (const float*)d_in[5];
    const float* bv = (const float*)d_in[6];
    float* out = (float*)d_out;

    dim3 g1(DMODEL / 64, (BATCH * NSEQ) / 64, 3);   // (8, 128, 3)
    qkv_kernel<<<g1, 256>>>(x, Wq, bq, Wk, bk, Wv, bv);

    dim3 g2(BATCH * NHEAD, NSEQ / 64);              // (64, 16)
    attn_kernel<<<g2, 256>>>(out);
}

// round 9
// speedup vs baseline: 1.0012x; 1.0012x over previous
#include <cuda_runtime.h>
#include <cuda_bf16.h>

#define BATCH   8
#define NSEQ    1024
#define DMODEL  512
#define NHEAD   8
#define DHEAD   64

// Scratch for Q/K/V projections (device globals: allocation-free)
__device__ float g_q[BATCH * NSEQ * DMODEL];
__device__ float g_k[BATCH * NSEQ * DMODEL];
__device__ float g_v[BATCH * NSEQ * DMODEL];

// ---------------------------------------------------------------------------
// Kernel 1: fused QKV projection.  Y = x @ W + b   (W stored [in, out])
// M = B*N = 8192, K = 512, Nout = 512.  blockIdx.z selects q/k/v.
// 64x64 output tile per block, 256 threads, 4x4 register tile per thread.
// ---------------------------------------------------------------------------
__global__ __launch_bounds__(256) void qkv_kernel(
    const float* __restrict__ x,
    const float* __restrict__ Wq, const float* __restrict__ bq,
    const float* __restrict__ Wk, const float* __restrict__ bk,
    const float* __restrict__ Wv, const float* __restrict__ bv)
{
    __shared__ float As[16 * 64];   // As[k][m]  (x tile, transposed)
    __shared__ float Bs[16 * 64];   // Bs[k][n]  (W tile, natural)

    const float* W; const float* bias; float* out;
    const int z = blockIdx.z;
    if (z == 0)      { W = Wq; bias = bq; out = g_q; }
    else if (z == 1) { W = Wk; bias = bk; out = g_k; }
    else             { W = Wv; bias = bv; out = g_v; }

    const int n0 = blockIdx.x * 64;
    const int m0 = blockIdx.y * 64;
    const int tid = threadIdx.x;
    const int tx = tid & 15, ty = tid >> 4;

    // A-load mapping: one float4 per thread per K-step
    const int am = tid >> 2;          // row within 64
    const int ak = (tid & 3) * 4;     // k segment start
    // B-load mapping: one float4 per thread per K-step
    const int bkr = tid >> 4;         // k row within 16
    const int bn  = (tid & 15) * 4;   // n segment start

    float acc[16];
    #pragma unroll
    for (int i = 0; i < 16; ++i) acc[i] = 0.f;

    for (int k0 = 0; k0 < DMODEL; k0 += 16) {
        const float4 a4 = *(const float4*)&x[(m0 + am) * DMODEL + k0 + ak];
        const float4 b4 = *(const float4*)&W[(k0 + bkr) * DMODEL + n0 + bn];
        __syncthreads();   // previous compute done reading smem
        As[(ak + 0) * 64 + am] = a4.x;
        As[(ak + 1) * 64 + am] = a4.y;
        As[(ak + 2) * 64 + am] = a4.z;
        As[(ak + 3) * 64 + am] = a4.w;
        *(float4*)&Bs[bkr * 64 + bn] = b4;
        __syncthreads();

        #pragma unroll
        for (int kk = 0; kk < 16; ++kk) {
            const float4 av = *(const float4*)&As[kk * 64 + 4 * ty];
            const float4 bv4 = *(const float4*)&Bs[kk * 64 + 4 * tx];
            acc[ 0] += av.x * bv4.x; acc[ 1] += av.x * bv4.y;
            acc[ 2] += av.x * bv4.z; acc[ 3] += av.x * bv4.w;
            acc[ 4] += av.y * bv4.x; acc[ 5] += av.y * bv4.y;
            acc[ 6] += av.y * bv4.z; acc[ 7] += av.y * bv4.w;
            acc[ 8] += av.z * bv4.x; acc[ 9] += av.z * bv4.y;
            acc[10] += av.z * bv4.z; acc[11] += av.z * bv4.w;
            acc[12] += av.w * bv4.x; acc[13] += av.w * bv4.y;
            acc[14] += av.w * bv4.z; acc[15] += av.w * bv4.w;
        }
    }

    const float4 bb = *(const float4*)&bias[n0 + 4 * tx];
    #pragma unroll
    for (int i = 0; i < 4; ++i) {
        float4 r;
        r.x = acc[4 * i + 0] + bb.x;
        r.y = acc[4 * i + 1] + bb.y;
        r.z = acc[4 * i + 2] + bb.z;
        r.w = acc[4 * i + 3] + bb.w;
        *(float4*)&out[(m0 + 4 * ty + i) * DMODEL + n0 + 4 * tx] = r;
    }
}

// ---------------------------------------------------------------------------
// Kernel 2: flash attention (no 1/sqrt(dh) scaling, per reference).
// One block per (b, h, 64-query tile). 256 threads, 4x4 register tiles.
// Smem: Qt (Q transposed, persistent), KP (K transposed, then aliased as P),
//       Vs (V natural). Exactly 48 KB static.
// ---------------------------------------------------------------------------
__global__ __launch_bounds__(256, 2) void attn_kernel(float* __restrict__ out)
{
    __shared__ float Qt[64 * 64];   // Qt[d][q]
    __shared__ float KP[64 * 64];   // Kt[d][k]  -> later P[q][k]
    __shared__ float Vs[64 * 64];   // Vs[k][d]

    const int bh = blockIdx.x;            // 0..63
    const int b = bh >> 3, h = bh & 7;
    const int q0 = blockIdx.y * 64;
    const int tid = threadIdx.x;
    const int tx = tid & 15, ty = tid >> 4;

    const float* qb = g_q + (b * NSEQ) * DMODEL + h * DHEAD;
    const float* kb = g_k + (b * NSEQ) * DMODEL + h * DHEAD;
    const float* vb = g_v + (b * NSEQ) * DMODEL + h * DHEAD;

    const int lr = tid >> 2;          // tile row this thread loads (0..63)
    const int ds = (tid & 3) * 16;    // d-segment start

    // Load Q tile transposed (once)
    {
        const float* src = qb + (q0 + lr) * DMODEL + ds;
        #pragma unroll
        for (int u = 0; u < 4; ++u) {
            const float4 v4 = *(const float4*)(src + 4 * u);
            const int d = ds + 4 * u;
            Qt[(d + 0) * 64 + lr] = v4.x;
            Qt[(d + 1) * 64 + lr] = v4.y;
            Qt[(d + 2) * 64 + lr] = v4.z;
            Qt[(d + 3) * 64 + lr] = v4.w;
        }
    }

    float o[16];
    #pragma unroll
    for (int i = 0; i < 16; ++i) o[i] = 0.f;
    float mrow[4] = {-1e30f, -1e30f, -1e30f, -1e30f};
    float lrow[4] = {0.f, 0.f, 0.f, 0.f};

    for (int kt = 0; kt < NSEQ / 64; ++kt) {
        const int k0 = kt * 64;
        __syncthreads();   // previous PV done reading KP/Vs (also covers Qt init)

        // Load K transposed + V natural
        {
            const float* ksrc = kb + (k0 + lr) * DMODEL + ds;
            const float* vsrc = vb + (k0 + lr) * DMODEL + ds;
            #pragma unroll
            for (int u = 0; u < 4; ++u) {
                const float4 v4 = *(const float4*)(ksrc + 4 * u);
                const int d = ds + 4 * u;
                KP[(d + 0) * 64 + lr] = v4.x;
                KP[(d + 1) * 64 + lr] = v4.y;
                KP[(d + 2) * 64 + lr] = v4.z;
                KP[(d + 3) * 64 + lr] = v4.w;
                *(float4*)&Vs[lr * 64 + ds + 4 * u] = *(const float4*)(vsrc + 4 * u);
            }
        }
        __syncthreads();

        // S = Q @ K^T  (no scaling)
        float s[16];
        #pragma unroll
        for (int i = 0; i < 16; ++i) s[i] = 0.f;
        #pragma unroll 8
        for (int d = 0; d < 64; ++d) {
            const float4 a = *(const float4*)&Qt[d * 64 + 4 * ty];
            const float4 c = *(const float4*)&KP[d * 64 + 4 * tx];
            s[ 0] += a.x * c.x; s[ 1] += a.x * c.y; s[ 2] += a.x * c.z; s[ 3] += a.x * c.w;
            s[ 4] += a.y * c.x; s[ 5] += a.y * c.y; s[ 6] += a.y * c.z; s[ 7] += a.y * c.w;
            s[ 8] += a.z * c.x; s[ 9] += a.z * c.y; s[10] += a.z * c.z; s[11] += a.z * c.w;
            s[12] += a.w * c.x; s[13] += a.w * c.y; s[14] += a.w * c.z; s[15] += a.w * c.w;
        }

        // Online softmax (row reductions across the 16 tx lanes of each half-warp)
        #pragma unroll
        for (int i = 0; i < 4; ++i) {
            float mt = fmaxf(fmaxf(s[4 * i + 0], s[4 * i + 1]),
                             fmaxf(s[4 * i + 2], s[4 * i + 3]));
            #pragma unroll
            for (int off = 1; off < 16; off <<= 1)
                mt = fmaxf(mt, __shfl_xor_sync(0xffffffffu, mt, off));
            const float mnew = fmaxf(mrow[i], mt);
            const float corr = __expf(mrow[i] - mnew);
            mrow[i] = mnew;
            float rs = 0.f;
            #pragma unroll
            for (int j = 0; j < 4; ++j) {
                const float p = __expf(s[4 * i + j] - mnew);
                s[4 * i + j] = p;
                rs += p;
            }
            #pragma unroll
            for (int off = 1; off < 16; off <<= 1)
                rs += __shfl_xor_sync(0xffffffffu, rs, off);
            lrow[i] = lrow[i] * corr + rs;
            #pragma unroll
            for (int j = 0; j < 4; ++j) o[4 * i + j] *= corr;
        }

        __syncthreads();   // all S reads of KP (as K) done
        // Write P into the dead K buffer, natural layout P[q][k]
        #pragma unroll
        for (int i = 0; i < 4; ++i)
            *(float4*)&KP[(4 * ty + i) * 64 + 4 * tx] =
                make_float4(s[4 * i + 0], s[4 * i + 1], s[4 * i + 2], s[4 * i + 3]);
        __syncthreads();

        // O += P @ V
        #pragma unroll 8
        for (int kk = 0; kk < 64; ++kk) {
            const float4 v4 = *(const float4*)&Vs[kk * 64 + 4 * tx];
            const float p0 = KP[(4 * ty + 0) * 64 + kk];
            const float p1 = KP[(4 * ty + 1) * 64 + kk];
            const float p2 = KP[(4 * ty + 2) * 64 + kk];
            const float p3 = KP[(4 * ty + 3) * 64 + kk];
            o[ 0] += p0 * v4.x; o[ 1] += p0 * v4.y; o[ 2] += p0 * v4.z; o[ 3] += p0 * v4.w;
            o[ 4] += p1 * v4.x; o[ 5] += p1 * v4.y; o[ 6] += p1 * v4.z; o[ 7] += p1 * v4.w;
            o[ 8] += p2 * v4.x; o[ 9] += p2 * v4.y; o[10] += p2 * v4.z; o[11] += p2 * v4.w;
            o[12] += p3 * v4.x; o[13] += p3 * v4.y; o[14] += p3 * v4.z; o[15] += p3 * v4.w;
        }
    }

    // Normalize and store
    float* ob = out + ((b * NSEQ) + q0) * DMODEL + h * DHEAD;
    #pragma unroll
    for (int i = 0; i < 4; ++i) {
        const float inv = 1.0f / lrow[i];
        const float4 r = make_float4(o[4 * i + 0] * inv, o[4 * i + 1] * inv,
                                     o[4 * i + 2] * inv, o[4 * i + 3] * inv);
        *(float4*)&ob[(4 * ty + i) * DMODEL + 4 * tx] = r;
    }
}

// ---------------------------------------------------------------------------
extern "C" void kernel_launch(void* const* d_in, const int* in_sizes, int n_in,
                              void* d_out, int out_size)
{
    (void)in_sizes; (void)n_in; (void)out_size;
    const float* x  = (const float*)d_in[0];
    const float* Wq = (const float*)d_in[1];
    const float* bq = (const float*)d_in[2];
    const float* Wk = (const float*)d_in[3];
    const float* bk = (const float*)d_in[4];
    const float* Wv = (const float*)d_in[5];
    const float* bv = (const float*)d_in[6];
    float* out = (float*)d_out;

    dim3 g1(DMODEL / 64, (BATCH * NSEQ) / 64, 3);   // (8, 128, 3)
    qkv_kernel<<<g1, 256>>>(x, Wq, bq, Wk, bk, Wv, bv);

    dim3 g2(BATCH * NHEAD, NSEQ / 64);              // (64, 16)
    attn_kernel<<<g2, 256>>>(out);
}